// round 12
// baseline (speedup 1.0000x reference)
#include <cuda_runtime.h>
#include <cuda_fp16.h>
#include <stdint.h>

// Fixed problem shapes
#define B_CONST     16
#define N_CONST     2048
#define S_CONST     4096
#define D_CONST     128
#define VOCAB_CONST 50257
#define NNZ_CONST   1048576
#define ROWS        (B_CONST * N_CONST)     // 32768 output rows
#define CAP         128                     // bucket capacity (Poisson(32); overflow ~ e^-81)

#define CONV_ELEMS8   ((int)((size_t)VOCAB_CONST * D_CONST / 8))   // 804112 uint4 groups

// One resident wave: 148 SMs x 12 blocks x 128 threads, guaranteed by
// __launch_bounds__(128, 12) (regs capped at 42). REQUIRED for the barrier.
#define TOTAL_BLOCKS  1776
#define FILL_PART     1392                  // ~78% of chip-work is the fill
#define CONV_PART     (TOTAL_BLOCKS - FILL_PART)
#define ACC_WARPS     (TOTAL_BLOCKS * 4)

// Static scratch (__device__ globals; zero-initialized at module load).
// Bucket entry: .x = byte offset of token's fp16 row (tok*256),
//               .y = half2(v, v) bits. Slots >= cnt never written -> zero.
__device__ uint2  g_bucket[(size_t)ROWS * CAP];               // 32 MB
__device__ int    g_cursor[ROWS];
__device__ __half g_htable[(size_t)VOCAB_CONST * D_CONST];    // 12.9 MB fp16 shadow
__device__ int    g_barrier;                                  // monotonic arrival counter

// ---------------------------------------------------------------------------
// Single persistent kernel:
//   Phase A: split block populations (fill || convert), grid-stride.
//   Device-wide barrier (monotonic counter -> replay-safe, no reset).
//   Phase B: one warp per row, grid-stride over rows; double-buffered LDG.64
//            gathers, HFMA2 accumulation, per-group fp32 flush.
// ---------------------------------------------------------------------------
__global__ __launch_bounds__(128, 12) void fused_kernel(
    const int*   __restrict__ subnode_ids,
    const int*   __restrict__ mask_batch,
    const int*   __restrict__ mask_node,
    const int*   __restrict__ mask_subnode,
    const float* __restrict__ mask_values,
    const float* __restrict__ emb_table,
    float*       __restrict__ out)
{
    const int blk = blockIdx.x;
    const int tid = threadIdx.x;

    // ================= Phase A =================
    if (blk < FILL_PART) {
        for (int i = blk * 128 + tid; i < NNZ_CONST; i += FILL_PART * 128) {
            const int   b    = __ldg(mask_batch   + i);
            const int   node = __ldg(mask_node    + i);
            const int   sub  = __ldg(mask_subnode + i);
            const float val  = __ldg(mask_values  + i);
            const int   tok  = __ldg(subnode_ids + b * S_CONST + sub);

            const int row = b * N_CONST + node;
            const int pos = atomicAdd(&g_cursor[row], 1);
            if (pos < CAP) {
                const __half  h  = __float2half_rn(val);
                const __half2 h2 = __halves2half2(h, h);
                uint2 e;
                e.x = (unsigned)tok * (D_CONST * 2);   // byte offset of fp16 row
                e.y = *reinterpret_cast<const unsigned*>(&h2);
                g_bucket[(size_t)row * CAP + pos] = e;
            }
        }
    } else {
        for (int j = (blk - FILL_PART) * 128 + tid; j < CONV_ELEMS8;
             j += CONV_PART * 128) {
            const float4 f0 = __ldg(reinterpret_cast<const float4*>(emb_table) + 2 * (size_t)j);
            const float4 f1 = __ldg(reinterpret_cast<const float4*>(emb_table) + 2 * (size_t)j + 1);
            __half2 h0 = __float22half2_rn(make_float2(f0.x, f0.y));
            __half2 h1 = __float22half2_rn(make_float2(f0.z, f0.w));
            __half2 h2 = __float22half2_rn(make_float2(f1.x, f1.y));
            __half2 h3 = __float22half2_rn(make_float2(f1.z, f1.w));
            uint4 u;
            u.x = *reinterpret_cast<unsigned*>(&h0);
            u.y = *reinterpret_cast<unsigned*>(&h1);
            u.z = *reinterpret_cast<unsigned*>(&h2);
            u.w = *reinterpret_cast<unsigned*>(&h3);
            reinterpret_cast<uint4*>(g_htable)[j] = u;
        }
    }

    // ================= Device-wide barrier =================
    // Monotonic counter: each replay adds exactly TOTAL_BLOCKS, so the
    // counter is a multiple of TOTAL_BLOCKS at replay start; no reset needed.
    __syncthreads();
    if (tid == 0) {
        __threadfence();                           // publish phase-A stores
        const int old    = atomicAdd(&g_barrier, 1);
        const int target = old - (old % TOTAL_BLOCKS) + TOTAL_BLOCKS;
        while ((int)(*(volatile int*)&g_barrier - target) < 0)
            __nanosleep(64);
    }
    __syncthreads();

    // ================= Phase B =================
    const int warp0 = blk * 4 + (tid >> 5);
    const int lane  = tid & 31;                    // D-halves [4*lane, 4*lane+4)
    const char* __restrict__ tabb =
        reinterpret_cast<const char*>(g_htable) + lane * 8;

    #define LOADG(BUF, G) do {                                                  \
        _Pragma("unroll")                                                       \
        for (int L = 0; L < 4; L++) {                                           \
            const unsigned off = __shfl_sync(0xffffffffu, e.x, (G)*4 + L);      \
            ub[BUF][L] = *reinterpret_cast<const uint2*>(tabb + off);           \
        }                                                                       \
    } while (0)

    #define CONSUME(BUF, G) do {                                                \
        __half2 h0 = __float2half2_rn(0.f), h1 = h0;                            \
        _Pragma("unroll")                                                       \
        for (int L = 0; L < 4; L++) {                                           \
            const unsigned vv = __shfl_sync(0xffffffffu, e.y, (G)*4 + L);       \
            const __half2 v2 = *reinterpret_cast<const __half2*>(&vv);          \
            const uint2   u  = ub[BUF][L];                                      \
            h0 = __hfma2(v2, *reinterpret_cast<const __half2*>(&u.x), h0);      \
            h1 = __hfma2(v2, *reinterpret_cast<const __half2*>(&u.y), h1);      \
        }                                                                       \
        float2 f;                                                               \
        f = __half22float2(h0); facc[0] += f.x; facc[1] += f.y;                 \
        f = __half22float2(h1); facc[2] += f.x; facc[3] += f.y;                 \
    } while (0)

    for (int row = warp0; row < ROWS; row += ACC_WARPS) {
        int cnt = g_cursor[row];
        cnt = cnt < CAP ? cnt : CAP;
        const uint2* __restrict__ p = g_bucket + (size_t)row * CAP;

        float facc[4];
        #pragma unroll
        for (int q = 0; q < 4; q++) facc[q] = 0.f;

        for (int base = 0; base < cnt; base += 32) {
            // Unconditional: slots >= cnt are zero (never written, any replay).
            const uint2 e = __ldg(p + base + lane);
            const int rem = cnt - base;

            uint2 ub[2][4];
            if (rem >= 32) {
                // Full batch: branch-free, fully unrolled 8-group pipeline.
                LOADG(0, 0);
                #pragma unroll
                for (int g = 0; g < 8; g++) {
                    if (g + 1 < 8) LOADG((g + 1) & 1, g + 1);   // const-folded
                    CONSUME(g & 1, g);
                }
            } else {
                const int ngrp = (rem + 3) >> 2;               // 1..7 groups
                LOADG(0, 0);
                int g = 0;
                while (true) {
                    if (g + 1 < ngrp) LOADG(1, g + 1);
                    CONSUME(0, g);
                    g++;
                    if (g >= ngrp) break;
                    if (g + 1 < ngrp) LOADG(0, g + 1);
                    CONSUME(1, g);
                    g++;
                    if (g >= ngrp) break;
                }
            }
        }

        *reinterpret_cast<float4*>(out + (size_t)row * D_CONST + lane * 4) =
            make_float4(facc[0], facc[1], facc[2], facc[3]);
        if (lane == 0) g_cursor[row] = 0;          // reset for next replay
    }
    #undef LOADG
    #undef CONSUME
}

// ---------------------------------------------------------------------------
// Inputs (metadata order):
//   0: subnode_ids [B*S] i32, 1: mask_batch [NNZ] i32, 2: mask_node [NNZ] i32,
//   3: mask_subnode [NNZ] i32, 4: mask_values [NNZ] f32, 5: emb_table [VOCAB*D] f32
// Output: [B*N*D] f32
// ---------------------------------------------------------------------------
extern "C" void kernel_launch(void* const* d_in, const int* in_sizes, int n_in,
                              void* d_out, int out_size) {
    const int*   subnode_ids  = (const int*)  d_in[0];
    const int*   mask_batch   = (const int*)  d_in[1];
    const int*   mask_node    = (const int*)  d_in[2];
    const int*   mask_subnode = (const int*)  d_in[3];
    const float* mask_values  = (const float*)d_in[4];
    const float* emb_table    = (const float*)d_in[5];
    float*       out          = (float*)d_out;

    fused_kernel<<<TOTAL_BLOCKS, 128>>>(
        subnode_ids, mask_batch, mask_node, mask_subnode,
        mask_values, emb_table, out);
}

// round 13
// speedup vs baseline: 1.2376x; 1.2376x over previous
#include <cuda_runtime.h>
#include <cuda_fp16.h>
#include <stdint.h>

// Fixed problem shapes
#define B_CONST     16
#define N_CONST     2048
#define S_CONST     4096
#define D_CONST     128
#define VOCAB_CONST 50257
#define NNZ_CONST   1048576
#define ROWS        (B_CONST * N_CONST)     // 32768 output rows
#define CAP         128                     // bucket capacity (Poisson(32); overflow ~ e^-81)

#define CONV_ELEMS8   ((int)((size_t)VOCAB_CONST * D_CONST / 8))   // 804112 uint4 groups

// Prep: 7168 blocks, roles interleaved mod 7 (4 fill : 3 convert) so every
// scheduling wave carries BOTH latency-bound fill and streaming convert.
#define PREP_GROUPS   1024
#define PREP_BLOCKS   (PREP_GROUPS * 7)     // 7168
#define FILL_BLOCKS   (PREP_GROUPS * 4)     // 4096 -> exactly 1 thread per nnz
#define CONV_BLOCKS   (PREP_GROUPS * 3)     // 3072, grid-stride over table

// Static scratch (__device__ globals; zero-initialized at module load).
// Bucket entry: .x = byte offset of token's fp16 row (tok*256),
//               .y = half2(v, v) bits. Slots >= cnt never written -> zero.
__device__ uint2  g_bucket[(size_t)ROWS * CAP];               // 32 MB
__device__ int    g_cursor[ROWS];
__device__ __half g_htable[(size_t)VOCAB_CONST * D_CONST];    // 12.9 MB fp16 shadow

// ---------------------------------------------------------------------------
// Phase 1: interleaved fill + convert.
//   blk % 7 < 4  -> fill slice   (dense index: (blk/7)*4 + blk%7)
//   blk % 7 >= 4 -> convert slice (dense index: (blk/7)*3 + blk%7 - 4)
// ---------------------------------------------------------------------------
__global__ __launch_bounds__(256) void prep_kernel(
    const int*   __restrict__ subnode_ids,
    const int*   __restrict__ mask_batch,
    const int*   __restrict__ mask_node,
    const int*   __restrict__ mask_subnode,
    const float* __restrict__ mask_values,
    const float* __restrict__ emb_table)
{
    const int grp = blockIdx.x / 7;
    const int rol = blockIdx.x % 7;

    if (rol < 4) {
        // ---- fill: exactly one nnz entry per thread ----
        const int i = (grp * 4 + rol) * 256 + threadIdx.x;
        const int   b    = __ldg(mask_batch   + i);
        const int   node = __ldg(mask_node    + i);
        const int   sub  = __ldg(mask_subnode + i);
        const float val  = __ldg(mask_values  + i);
        const int   tok  = __ldg(subnode_ids + b * S_CONST + sub);

        const int row = b * N_CONST + node;
        const int pos = atomicAdd(&g_cursor[row], 1);
        if (pos < CAP) {
            const __half  h  = __float2half_rn(val);
            const __half2 h2 = __halves2half2(h, h);
            uint2 e;
            e.x = (unsigned)tok * (D_CONST * 2);   // byte offset of fp16 row
            e.y = *reinterpret_cast<const unsigned*>(&h2);
            g_bucket[(size_t)row * CAP + pos] = e;
        }
    } else {
        // ---- convert: grid-stride, 8 floats per iteration ----
        const int cblk = grp * 3 + (rol - 4);
        for (int j = cblk * 256 + threadIdx.x; j < CONV_ELEMS8;
             j += CONV_BLOCKS * 256) {
            const float4 f0 = __ldg(reinterpret_cast<const float4*>(emb_table) + 2 * (size_t)j);
            const float4 f1 = __ldg(reinterpret_cast<const float4*>(emb_table) + 2 * (size_t)j + 1);
            __half2 h0 = __float22half2_rn(make_float2(f0.x, f0.y));
            __half2 h1 = __float22half2_rn(make_float2(f0.z, f0.w));
            __half2 h2 = __float22half2_rn(make_float2(f1.x, f1.y));
            __half2 h3 = __float22half2_rn(make_float2(f1.z, f1.w));
            uint4 u;
            u.x = *reinterpret_cast<unsigned*>(&h0);
            u.y = *reinterpret_cast<unsigned*>(&h1);
            u.z = *reinterpret_cast<unsigned*>(&h2);
            u.w = *reinterpret_cast<unsigned*>(&h3);
            reinterpret_cast<uint4*>(g_htable)[j] = u;
        }
    }
}

// ---------------------------------------------------------------------------
// Phase 2: ONE warp per row. One entry = one LDG.64 by the full warp
// (32 lanes x 8B = the 256B fp16 row); bucket holds byte offsets. 4-entry
// groups double-buffered (8 loads in flight); HFMA2 accumulation, per-group
// fp32 flush. Full 32-entry batches take a branch-free fully-unrolled path.
// Block = 128 threads = 4 rows, 12 blocks/SM.
// ---------------------------------------------------------------------------
__global__ __launch_bounds__(128, 12) void accumulate_kernel(
    float* __restrict__ out)   // [B*N, D]
{
    const int wib  = threadIdx.x >> 5;      // warp in block: 0..3
    const int row  = blockIdx.x * 4 + wib;
    const int lane = threadIdx.x & 31;      // D-halves [4*lane, 4*lane+4)
    const char* __restrict__ tabb =
        reinterpret_cast<const char*>(g_htable) + lane * 8;

    int cnt = g_cursor[row];
    cnt = cnt < CAP ? cnt : CAP;
    const uint2* __restrict__ p = g_bucket + (size_t)row * CAP;

    float facc[4];
    #pragma unroll
    for (int q = 0; q < 4; q++) facc[q] = 0.f;

    #define LOADG(BUF, G) do {                                                  \
        _Pragma("unroll")                                                       \
        for (int L = 0; L < 4; L++) {                                           \
            const unsigned off = __shfl_sync(0xffffffffu, e.x, (G)*4 + L);      \
            ub[BUF][L] = *reinterpret_cast<const uint2*>(tabb + off);           \
        }                                                                       \
    } while (0)

    #define CONSUME(BUF, G) do {                                                \
        __half2 h0 = __float2half2_rn(0.f), h1 = h0;                            \
        _Pragma("unroll")                                                       \
        for (int L = 0; L < 4; L++) {                                           \
            const unsigned vv = __shfl_sync(0xffffffffu, e.y, (G)*4 + L);       \
            const __half2 v2 = *reinterpret_cast<const __half2*>(&vv);          \
            const uint2   u  = ub[BUF][L];                                      \
            h0 = __hfma2(v2, *reinterpret_cast<const __half2*>(&u.x), h0);      \
            h1 = __hfma2(v2, *reinterpret_cast<const __half2*>(&u.y), h1);      \
        }                                                                       \
        float2 f;                                                               \
        f = __half22float2(h0); facc[0] += f.x; facc[1] += f.y;                 \
        f = __half22float2(h1); facc[2] += f.x; facc[3] += f.y;                 \
    } while (0)

    for (int base = 0; base < cnt; base += 32) {
        // Unconditional: slots >= cnt are zero (never written in any replay).
        const uint2 e = __ldg(p + base + lane);
        const int rem = cnt - base;

        uint2 ub[2][4];
        if (rem >= 32) {
            // Full batch: branch-free, fully unrolled 8-group pipeline.
            LOADG(0, 0);
            #pragma unroll
            for (int g = 0; g < 8; g++) {
                if (g + 1 < 8) LOADG((g + 1) & 1, g + 1);   // const-folded
                CONSUME(g & 1, g);
            }
        } else {
            const int ngrp = (rem + 3) >> 2;               // 1..7 groups of 4
            LOADG(0, 0);
            int g = 0;
            while (true) {
                if (g + 1 < ngrp) LOADG(1, g + 1);
                CONSUME(0, g);
                g++;
                if (g >= ngrp) break;
                if (g + 1 < ngrp) LOADG(0, g + 1);
                CONSUME(1, g);
                g++;
                if (g >= ngrp) break;
            }
        }
    }
    #undef LOADG
    #undef CONSUME

    *reinterpret_cast<float4*>(out + (size_t)row * D_CONST + lane * 4) =
        make_float4(facc[0], facc[1], facc[2], facc[3]);
    if (lane == 0) g_cursor[row] = 0;       // reset for next graph replay
}

// ---------------------------------------------------------------------------
// Inputs (metadata order):
//   0: subnode_ids [B*S] i32, 1: mask_batch [NNZ] i32, 2: mask_node [NNZ] i32,
//   3: mask_subnode [NNZ] i32, 4: mask_values [NNZ] f32, 5: emb_table [VOCAB*D] f32
// Output: [B*N*D] f32
// ---------------------------------------------------------------------------
extern "C" void kernel_launch(void* const* d_in, const int* in_sizes, int n_in,
                              void* d_out, int out_size) {
    const int*   subnode_ids  = (const int*)  d_in[0];
    const int*   mask_batch   = (const int*)  d_in[1];
    const int*   mask_node    = (const int*)  d_in[2];
    const int*   mask_subnode = (const int*)  d_in[3];
    const float* mask_values  = (const float*)d_in[4];
    const float* emb_table    = (const float*)d_in[5];
    float*       out          = (float*)d_out;

    prep_kernel<<<PREP_BLOCKS, 256>>>(
        subnode_ids, mask_batch, mask_node, mask_subnode, mask_values, emb_table);

    accumulate_kernel<<<ROWS / 4, 128>>>(out);
}

// round 14
// speedup vs baseline: 1.2422x; 1.0037x over previous
#include <cuda_runtime.h>
#include <cuda_fp16.h>
#include <stdint.h>

// Fixed problem shapes
#define B_CONST     16
#define N_CONST     2048
#define S_CONST     4096
#define D_CONST     128
#define VOCAB_CONST 50257
#define NNZ_CONST   1048576
#define ROWS        (B_CONST * N_CONST)     // 32768 output rows
#define CAP         128                     // bucket capacity (Poisson(32); overflow ~ e^-81)

#define FILL_BLOCKS   (NNZ_CONST / 256)                       // 4096
#define CONV_ELEMS8   ((int)((size_t)VOCAB_CONST * D_CONST / 8))
#define CONV_BLOCKS   ((CONV_ELEMS8 + 255) / 256)

// Static scratch (__device__ globals; zero-initialized at module load).
// Bucket entry: .x = byte offset of token's fp16 row (tok*256),
//               .y = half2(v, v) bits. Slots >= cnt never written -> zero.
__device__ uint2  g_bucket[(size_t)ROWS * CAP];               // 32 MB
__device__ int    g_cursor[ROWS];
__device__ __half g_htable[(size_t)VOCAB_CONST * D_CONST];    // 12.9 MB fp16 shadow

// ---------------------------------------------------------------------------
// Phase 1 (R9's proven split-population form): blocks [0, FILL_BLOCKS) bucket
// nnz entries; remaining blocks convert emb_table fp32 -> fp16.
// ---------------------------------------------------------------------------
__global__ __launch_bounds__(256) void prep_kernel(
    const int*   __restrict__ subnode_ids,
    const int*   __restrict__ mask_batch,
    const int*   __restrict__ mask_node,
    const int*   __restrict__ mask_subnode,
    const float* __restrict__ mask_values,
    const float* __restrict__ emb_table)
{
    const int blk = blockIdx.x;
    if (blk < FILL_BLOCKS) {
        const int i = blk * 256 + threadIdx.x;
        const int   b    = __ldg(mask_batch   + i);
        const int   node = __ldg(mask_node    + i);
        const int   sub  = __ldg(mask_subnode + i);
        const float val  = __ldg(mask_values  + i);
        const int   tok  = __ldg(subnode_ids + b * S_CONST + sub);

        const int row = b * N_CONST + node;
        const int pos = atomicAdd(&g_cursor[row], 1);
        if (pos < CAP) {
            const __half  h  = __float2half_rn(val);
            const __half2 h2 = __halves2half2(h, h);
            uint2 e;
            e.x = (unsigned)tok * (D_CONST * 2);   // byte offset of fp16 row
            e.y = *reinterpret_cast<const unsigned*>(&h2);
            g_bucket[(size_t)row * CAP + pos] = e;
        }
    } else {
        const int j = (blk - FILL_BLOCKS) * 256 + threadIdx.x;
        if (j < CONV_ELEMS8) {
            const float4 f0 = __ldg(reinterpret_cast<const float4*>(emb_table) + 2 * (size_t)j);
            const float4 f1 = __ldg(reinterpret_cast<const float4*>(emb_table) + 2 * (size_t)j + 1);
            __half2 h0 = __float22half2_rn(make_float2(f0.x, f0.y));
            __half2 h1 = __float22half2_rn(make_float2(f0.z, f0.w));
            __half2 h2 = __float22half2_rn(make_float2(f1.x, f1.y));
            __half2 h3 = __float22half2_rn(make_float2(f1.z, f1.w));
            uint4 u;
            u.x = *reinterpret_cast<unsigned*>(&h0);
            u.y = *reinterpret_cast<unsigned*>(&h1);
            u.z = *reinterpret_cast<unsigned*>(&h2);
            u.w = *reinterpret_cast<unsigned*>(&h3);
            reinterpret_cast<uint4*>(g_htable)[j] = u;
        }
    }
}

// ---------------------------------------------------------------------------
// Phase 2: ONE warp per row; half-warp hw takes alternate entries, lane
// covers bytes [16*(lane&15), 16*(lane&15)+16) of each 256B fp16 row via
// LDG.128. One LDG.128 / tok-shfl / vv-shfl serves TWO entries -> ~6
// instrs/entry. Groups of 4 entries (2 LDG.128) double-buffered (4 loads,
// 8 entries in flight); half2 partials flushed to fp32 every 2 groups.
// End: shfl_xor(16) butterfly merges hw-partitions; one STG.128 per lane.
// Block = 128 threads = 4 rows, 12 blocks/SM.
// ---------------------------------------------------------------------------
__global__ __launch_bounds__(128, 12) void accumulate_kernel(
    float* __restrict__ out)   // [B*N, D]
{
    const int wib  = threadIdx.x >> 5;      // warp in block: 0..3
    const int row  = blockIdx.x * 4 + wib;
    const int lane = threadIdx.x & 31;
    const int hw   = lane >> 4;             // entry parity within group
    const int sub  = lane & 15;             // 16B segment of the row
    const char* __restrict__ tabb =
        reinterpret_cast<const char*>(g_htable) + sub * 16;

    int cnt = g_cursor[row];
    cnt = cnt < CAP ? cnt : CAP;
    const uint2* __restrict__ p = g_bucket + (size_t)row * CAP;

    float facc[8];
    #pragma unroll
    for (int q = 0; q < 8; q++) facc[q] = 0.f;

    // Group G = 4 entries = 2 LDG.128 (each covers 2 entries via hw).
    #define LOADG(BUF, G) do {                                                  \
        _Pragma("unroll")                                                       \
        for (int L = 0; L < 2; L++) {                                           \
            const int idx = (G) * 4 + L * 2 + hw;                               \
            const unsigned off = __shfl_sync(0xffffffffu, e.x, idx);            \
            ub[BUF][L] = *reinterpret_cast<const uint4*>(tabb + off);           \
        }                                                                       \
    } while (0)

    // Accumulate group G's entries into hacc (no flush).
    #define CONS(BUF, G) do {                                                   \
        _Pragma("unroll")                                                       \
        for (int L = 0; L < 2; L++) {                                           \
            const int idx = (G) * 4 + L * 2 + hw;                               \
            const unsigned vv = __shfl_sync(0xffffffffu, e.y, idx);             \
            const __half2 v2 = *reinterpret_cast<const __half2*>(&vv);          \
            const uint4   u  = ub[BUF][L];                                      \
            hacc0 = __hfma2(v2, *reinterpret_cast<const __half2*>(&u.x), hacc0);\
            hacc1 = __hfma2(v2, *reinterpret_cast<const __half2*>(&u.y), hacc1);\
            hacc2 = __hfma2(v2, *reinterpret_cast<const __half2*>(&u.z), hacc2);\
            hacc3 = __hfma2(v2, *reinterpret_cast<const __half2*>(&u.w), hacc3);\
        }                                                                       \
    } while (0)

    for (int base = 0; base < cnt; base += 32) {
        // Unconditional: slots >= cnt are zero (never written in any replay).
        const uint2 e = __ldg(p + base + lane);
        const int rem  = cnt - base;
        const int ngrp = rem < 32 ? ((rem + 3) >> 2) : 8;   // 1..8 groups of 4

        uint4 ub[2][2];
        LOADG(0, 0);
        int g = 0;
        while (true) {
            __half2 hacc0 = __float2half2_rn(0.f);
            __half2 hacc1 = hacc0, hacc2 = hacc0, hacc3 = hacc0;
            if (g + 1 < ngrp) LOADG(1, g + 1);
            CONS(0, g);
            g++;
            if (g < ngrp) {
                if (g + 1 < ngrp) LOADG(0, g + 1);
                CONS(1, g);
                g++;
            }
            // Flush 8 entries' worth of half2 partials to fp32
            float2 f;
            f = __half22float2(hacc0); facc[0] += f.x; facc[1] += f.y;
            f = __half22float2(hacc1); facc[2] += f.x; facc[3] += f.y;
            f = __half22float2(hacc2); facc[4] += f.x; facc[5] += f.y;
            f = __half22float2(hacc3); facc[6] += f.x; facc[7] += f.y;
            if (g >= ngrp) break;
        }
    }
    #undef LOADG
    #undef CONS

    // Merge even-entry (hw=0) and odd-entry (hw=1) partial sums
    #pragma unroll
    for (int q = 0; q < 8; q++)
        facc[q] += __shfl_xor_sync(0xffffffffu, facc[q], 16);

    // Lane (hw, sub) writes float4 at float offset sub*8 + hw*4
    float4 st;
    if (hw == 0) st = make_float4(facc[0], facc[1], facc[2], facc[3]);
    else         st = make_float4(facc[4], facc[5], facc[6], facc[7]);
    *reinterpret_cast<float4*>(out + (size_t)row * D_CONST + sub * 8 + hw * 4) = st;

    if (lane == 0) g_cursor[row] = 0;       // reset for next graph replay
}

// ---------------------------------------------------------------------------
// Inputs (metadata order):
//   0: subnode_ids [B*S] i32, 1: mask_batch [NNZ] i32, 2: mask_node [NNZ] i32,
//   3: mask_subnode [NNZ] i32, 4: mask_values [NNZ] f32, 5: emb_table [VOCAB*D] f32
// Output: [B*N*D] f32
// ---------------------------------------------------------------------------
extern "C" void kernel_launch(void* const* d_in, const int* in_sizes, int n_in,
                              void* d_out, int out_size) {
    const int*   subnode_ids  = (const int*)  d_in[0];
    const int*   mask_batch   = (const int*)  d_in[1];
    const int*   mask_node    = (const int*)  d_in[2];
    const int*   mask_subnode = (const int*)  d_in[3];
    const float* mask_values  = (const float*)d_in[4];
    const float* emb_table    = (const float*)d_in[5];
    float*       out          = (float*)d_out;

    prep_kernel<<<FILL_BLOCKS + CONV_BLOCKS, 256>>>(
        subnode_ids, mask_batch, mask_node, mask_subnode, mask_values, emb_table);

    accumulate_kernel<<<ROWS / 4, 128>>>(out);
}

// round 15
// speedup vs baseline: 1.2829x; 1.0327x over previous
#include <cuda_runtime.h>
#include <cuda_fp16.h>
#include <stdint.h>

// Fixed problem shapes
#define B_CONST     16
#define N_CONST     2048
#define S_CONST     4096
#define D_CONST     128
#define VOCAB_CONST 50257
#define NNZ_CONST   1048576
#define ROWS        (B_CONST * N_CONST)     // 32768 output rows
#define CAP         128                     // bucket capacity (Poisson(32); overflow ~ e^-81)

#define FILL_BLOCKS   (NNZ_CONST / 256)                       // 4096
#define CONV_ELEMS8   ((int)((size_t)VOCAB_CONST * D_CONST / 8))
#define CONV_BLOCKS   ((CONV_ELEMS8 + 255) / 256)

// Static scratch (__device__ globals; zero-initialized at module load).
// Bucket entry: .x = token id, .y = half2(v, v) bits. Slots >= cnt never
// written in any replay -> stay zero.
__device__ uint2  g_bucket[(size_t)ROWS * CAP];               // 32 MB
__device__ int    g_cursor[ROWS];
__device__ __half g_htable[(size_t)VOCAB_CONST * D_CONST];    // 12.9 MB fp16 shadow

// ---------------------------------------------------------------------------
// Phase 1 (exact R9 form, proven): blocks [0, FILL_BLOCKS) bucket nnz
// entries; remaining blocks convert emb_table fp32 -> fp16 (8 floats/thread).
// Ends with a PDL trigger so the accumulate launch can begin during our tail.
// ---------------------------------------------------------------------------
__global__ __launch_bounds__(256) void prep_kernel(
    const int*   __restrict__ subnode_ids,
    const int*   __restrict__ mask_batch,
    const int*   __restrict__ mask_node,
    const int*   __restrict__ mask_subnode,
    const float* __restrict__ mask_values,
    const float* __restrict__ emb_table)
{
    const int blk = blockIdx.x;
    if (blk < FILL_BLOCKS) {
        const int i = blk * 256 + threadIdx.x;
        const int   b    = __ldg(mask_batch   + i);
        const int   node = __ldg(mask_node    + i);
        const int   sub  = __ldg(mask_subnode + i);
        const float val  = __ldg(mask_values  + i);
        const int   tok  = __ldg(subnode_ids + b * S_CONST + sub);

        const int row = b * N_CONST + node;
        const int pos = atomicAdd(&g_cursor[row], 1);
        if (pos < CAP) {
            const __half  h  = __float2half_rn(val);
            const __half2 h2 = __halves2half2(h, h);
            uint2 e;
            e.x = (unsigned)tok;
            e.y = *reinterpret_cast<const unsigned*>(&h2);
            g_bucket[(size_t)row * CAP + pos] = e;
        }
    } else {
        const int j = (blk - FILL_BLOCKS) * 256 + threadIdx.x;
        if (j < CONV_ELEMS8) {
            const float4 f0 = __ldg(reinterpret_cast<const float4*>(emb_table) + 2 * (size_t)j);
            const float4 f1 = __ldg(reinterpret_cast<const float4*>(emb_table) + 2 * (size_t)j + 1);
            __half2 h0 = __float22half2_rn(make_float2(f0.x, f0.y));
            __half2 h1 = __float22half2_rn(make_float2(f0.z, f0.w));
            __half2 h2 = __float22half2_rn(make_float2(f1.x, f1.y));
            __half2 h3 = __float22half2_rn(make_float2(f1.z, f1.w));
            uint4 u;
            u.x = *reinterpret_cast<unsigned*>(&h0);
            u.y = *reinterpret_cast<unsigned*>(&h1);
            u.z = *reinterpret_cast<unsigned*>(&h2);
            u.w = *reinterpret_cast<unsigned*>(&h3);
            reinterpret_cast<uint4*>(g_htable)[j] = u;
        }
    }
    // Allow the dependent (accumulate) grid to begin launching.
    cudaTriggerProgrammaticLaunchCompletion();
}

// ---------------------------------------------------------------------------
// Phase 2 (exact R9 form, proven 29.5us): ONE warp per row. One entry = one
// LDG.64 by the full warp (32 lanes x 8B = the 256B fp16 row). 4-entry groups
// double-buffered (8 loads in flight); HFMA2 accumulation, per-group fp32
// flush. Block = 128 threads = 4 rows, 12 blocks/SM.
// Gated on prep completion via PDL grid-dependency sync.
// ---------------------------------------------------------------------------
__global__ __launch_bounds__(128, 12) void accumulate_kernel(
    float* __restrict__ out)   // [B*N, D]
{
    cudaGridDependencySynchronize();        // wait for prep's stores

    const int wib  = threadIdx.x >> 5;      // warp in block: 0..3
    const int row  = blockIdx.x * 4 + wib;
    const int lane = threadIdx.x & 31;      // D-halves [4*lane, 4*lane+4)

    int cnt = g_cursor[row];
    cnt = cnt < CAP ? cnt : CAP;

    const uint2* __restrict__ p = g_bucket + (size_t)row * CAP;
    const __half* __restrict__ tab = g_htable;

    float facc[4];
    #pragma unroll
    for (int q = 0; q < 4; q++) facc[q] = 0.f;

    #define LOADG(BUF, G) do {                                                  \
        _Pragma("unroll")                                                       \
        for (int L = 0; L < 4; L++) {                                           \
            const unsigned tk = __shfl_sync(0xffffffffu, e.x, (G) * 4 + L);     \
            ub[BUF][L] = *reinterpret_cast<const uint2*>(                       \
                tab + (size_t)tk * D_CONST + lane * 4);                         \
        }                                                                       \
    } while (0)

    #define CONSUME(BUF, G) do {                                                \
        __half2 h0 = __float2half2_rn(0.f), h1 = h0;                            \
        _Pragma("unroll")                                                       \
        for (int L = 0; L < 4; L++) {                                           \
            const unsigned vv = __shfl_sync(0xffffffffu, e.y, (G) * 4 + L);     \
            const __half2 v2 = *reinterpret_cast<const __half2*>(&vv);          \
            const uint2   u  = ub[BUF][L];                                      \
            h0 = __hfma2(v2, *reinterpret_cast<const __half2*>(&u.x), h0);      \
            h1 = __hfma2(v2, *reinterpret_cast<const __half2*>(&u.y), h1);      \
        }                                                                       \
        float2 f;                                                               \
        f = __half22float2(h0); facc[0] += f.x; facc[1] += f.y;                 \
        f = __half22float2(h1); facc[2] += f.x; facc[3] += f.y;                 \
    } while (0)

    for (int base = 0; base < cnt; base += 32) {
        const int rem = cnt - base;
        const int nb  = rem < 32 ? rem : 32;
        uint2 e = make_uint2(0u, 0u);                 // padding: tok 0, v 0
        if (lane < nb) e = __ldg(p + base + lane);
        const int ngrp = (nb + 3) >> 2;               // 1..8 groups of 4

        uint2 ub[2][4];

        LOADG(0, 0);
        int g = 0;
        while (true) {
            if (g + 1 < ngrp) LOADG(1, g + 1);
            CONSUME(0, g);
            g++;
            if (g >= ngrp) break;
            if (g + 1 < ngrp) LOADG(0, g + 1);
            CONSUME(1, g);
            g++;
            if (g >= ngrp) break;
        }
    }
    #undef LOADG
    #undef CONSUME

    *reinterpret_cast<float4*>(out + (size_t)row * D_CONST + lane * 4) =
        make_float4(facc[0], facc[1], facc[2], facc[3]);
    if (lane == 0) g_cursor[row] = 0;       // reset for next graph replay
}

// ---------------------------------------------------------------------------
// Inputs (metadata order):
//   0: subnode_ids [B*S] i32, 1: mask_batch [NNZ] i32, 2: mask_node [NNZ] i32,
//   3: mask_subnode [NNZ] i32, 4: mask_values [NNZ] f32, 5: emb_table [VOCAB*D] f32
// Output: [B*N*D] f32
// ---------------------------------------------------------------------------
extern "C" void kernel_launch(void* const* d_in, const int* in_sizes, int n_in,
                              void* d_out, int out_size) {
    const int*   subnode_ids  = (const int*)  d_in[0];
    const int*   mask_batch   = (const int*)  d_in[1];
    const int*   mask_node    = (const int*)  d_in[2];
    const int*   mask_subnode = (const int*)  d_in[3];
    const float* mask_values  = (const float*)d_in[4];
    const float* emb_table    = (const float*)d_in[5];
    float*       out          = (float*)d_out;

    prep_kernel<<<FILL_BLOCKS + CONV_BLOCKS, 256>>>(
        subnode_ids, mask_batch, mask_node, mask_subnode, mask_values, emb_table);

    // Accumulate with Programmatic Dependent Launch: scheduled while prep
    // drains; cudaGridDependencySynchronize() inside gates the actual reads.
    cudaLaunchConfig_t cfg = {};
    cfg.gridDim  = dim3(ROWS / 4);
    cfg.blockDim = dim3(128);
    cfg.dynamicSmemBytes = 0;
    cfg.stream = 0;                          // legacy default stream (captured)
    cudaLaunchAttribute attrs[1];
    attrs[0].id = cudaLaunchAttributeProgrammaticStreamSerialization;
    attrs[0].val.programmaticStreamSerializationAllowed = 1;
    cfg.attrs = attrs;
    cfg.numAttrs = 1;
    cudaLaunchKernelEx(&cfg, accumulate_kernel, out);
}

// round 16
// speedup vs baseline: 1.3236x; 1.0318x over previous
#include <cuda_runtime.h>
#include <cuda_fp16.h>
#include <stdint.h>

// Fixed problem shapes
#define B_CONST     16
#define N_CONST     2048
#define S_CONST     4096
#define D_CONST     128
#define VOCAB_CONST 50257
#define NNZ_CONST   1048576
#define ROWS        (B_CONST * N_CONST)     // 32768 output rows
#define CAP         128                     // bucket capacity (Poisson(32); overflow ~ e^-81)

#define FILL_BLOCKS   (NNZ_CONST / 256)                       // 4096
#define CONV_ELEMS8   ((int)((size_t)VOCAB_CONST * D_CONST / 8))
#define CONV_BLOCKS   ((CONV_ELEMS8 + 255) / 256)

// Static scratch (__device__ globals; zero-initialized at module load).
// Packed bucket entry (4B): high 16 = token id (< 50257 < 2^16),
//                           low 16  = fp16 value bits.
// Slots >= cnt are never written in any replay -> stay zero
// (zero entry = token 0, value 0 -> harmless weight-0 gather of row 0).
__device__ unsigned g_bucket[(size_t)ROWS * CAP];             // 16 MB
__device__ int      g_cursor[ROWS];
__device__ __half   g_htable[(size_t)VOCAB_CONST * D_CONST];  // 12.9 MB fp16 shadow

// ---------------------------------------------------------------------------
// Phase 1: blocks [0, FILL_BLOCKS) bucket nnz entries (4B packed stores);
// remaining blocks convert emb_table fp32 -> fp16 (8 floats/thread).
// Ends with a PDL trigger so the accumulate launch overlaps our tail.
// ---------------------------------------------------------------------------
__global__ __launch_bounds__(256) void prep_kernel(
    const int*   __restrict__ subnode_ids,
    const int*   __restrict__ mask_batch,
    const int*   __restrict__ mask_node,
    const int*   __restrict__ mask_subnode,
    const float* __restrict__ mask_values,
    const float* __restrict__ emb_table)
{
    const int blk = blockIdx.x;
    if (blk < FILL_BLOCKS) {
        const int i = blk * 256 + threadIdx.x;
        const int   b    = __ldg(mask_batch   + i);
        const int   node = __ldg(mask_node    + i);
        const int   sub  = __ldg(mask_subnode + i);
        const float val  = __ldg(mask_values  + i);
        const int   tok  = __ldg(subnode_ids + b * S_CONST + sub);

        const int row = b * N_CONST + node;
        const int pos = atomicAdd(&g_cursor[row], 1);
        if (pos < CAP) {
            const unsigned hbits =
                (unsigned)__half_as_ushort(__float2half_rn(val));
            g_bucket[(size_t)row * CAP + pos] =
                ((unsigned)tok << 16) | hbits;             // one ST.32
        }
    } else {
        const int j = (blk - FILL_BLOCKS) * 256 + threadIdx.x;
        if (j < CONV_ELEMS8) {
            const float4 f0 = __ldg(reinterpret_cast<const float4*>(emb_table) + 2 * (size_t)j);
            const float4 f1 = __ldg(reinterpret_cast<const float4*>(emb_table) + 2 * (size_t)j + 1);
            __half2 h0 = __float22half2_rn(make_float2(f0.x, f0.y));
            __half2 h1 = __float22half2_rn(make_float2(f0.z, f0.w));
            __half2 h2 = __float22half2_rn(make_float2(f1.x, f1.y));
            __half2 h3 = __float22half2_rn(make_float2(f1.z, f1.w));
            uint4 u;
            u.x = *reinterpret_cast<unsigned*>(&h0);
            u.y = *reinterpret_cast<unsigned*>(&h1);
            u.z = *reinterpret_cast<unsigned*>(&h2);
            u.w = *reinterpret_cast<unsigned*>(&h3);
            reinterpret_cast<uint4*>(g_htable)[j] = u;
        }
    }
    cudaTriggerProgrammaticLaunchCompletion();
}

// ---------------------------------------------------------------------------
// Phase 2: ONE warp per row. One entry = one LDG.64 by the full warp
// (32 lanes x 8B = the 256B fp16 row). Each entry needs ONE shuffle of the
// packed word: address = (w>>8)&0xFFFF00 (SHF+LOP3, off the MIO port),
// value half2(v,v) = PRMT(w,w,0x1010). 4-entry groups double-buffered
// (8 loads in flight); HFMA2 accumulation, per-group fp32 flush.
// Block = 128 threads = 4 rows, 12 blocks/SM. PDL-gated on prep.
// ---------------------------------------------------------------------------
__global__ __launch_bounds__(128, 12) void accumulate_kernel(
    float* __restrict__ out)   // [B*N, D]
{
    cudaGridDependencySynchronize();        // wait for prep's stores

    const int wib  = threadIdx.x >> 5;      // warp in block: 0..3
    const int row  = blockIdx.x * 4 + wib;
    const int lane = threadIdx.x & 31;      // D-halves [4*lane, 4*lane+4)

    int cnt = g_cursor[row];
    cnt = cnt < CAP ? cnt : CAP;

    const unsigned* __restrict__ p = g_bucket + (size_t)row * CAP;
    const char* __restrict__ tabb =
        reinterpret_cast<const char*>(g_htable) + lane * 8;

    float facc[4];
    #pragma unroll
    for (int q = 0; q < 4; q++) facc[q] = 0.f;

    // Group G = 4 entries; one LDG.64 per entry (full warp reads the row).
    // Byte offset of token's row: tok*256 = (w >> 16) << 8 = (w >> 8) & 0xFFFF00.
    #define LOADG(BUF, G) do {                                                  \
        _Pragma("unroll")                                                       \
        for (int L = 0; L < 4; L++) {                                           \
            const unsigned w = __shfl_sync(0xffffffffu, e, (G) * 4 + L);        \
            const unsigned off = (w >> 8) & 0x00FFFF00u;                        \
            ub[BUF][L] = *reinterpret_cast<const uint2*>(tabb + off);           \
        }                                                                       \
    } while (0)

    #define CONSUME(BUF, G) do {                                                \
        __half2 h0 = __float2half2_rn(0.f), h1 = h0;                            \
        _Pragma("unroll")                                                       \
        for (int L = 0; L < 4; L++) {                                           \
            const unsigned w = __shfl_sync(0xffffffffu, e, (G) * 4 + L);        \
            const unsigned vvb = __byte_perm(w, w, 0x1010);  /* (v,v) */        \
            const __half2 v2 = *reinterpret_cast<const __half2*>(&vvb);         \
            const uint2   u  = ub[BUF][L];                                      \
            h0 = __hfma2(v2, *reinterpret_cast<const __half2*>(&u.x), h0);      \
            h1 = __hfma2(v2, *reinterpret_cast<const __half2*>(&u.y), h1);      \
        }                                                                       \
        float2 f;                                                               \
        f = __half22float2(h0); facc[0] += f.x; facc[1] += f.y;                 \
        f = __half22float2(h1); facc[2] += f.x; facc[3] += f.y;                 \
    } while (0)

    for (int base = 0; base < cnt; base += 32) {
        // Unconditional: slots >= cnt are zero (never written in any replay).
        const unsigned e = __ldg(p + base + lane);
        const int rem  = cnt - base;
        const int ngrp = rem < 32 ? ((rem + 3) >> 2) : 8;   // 1..8 groups of 4

        uint2 ub[2][4];

        LOADG(0, 0);
        int g = 0;
        while (true) {
            if (g + 1 < ngrp) LOADG(1, g + 1);
            CONSUME(0, g);
            g++;
            if (g >= ngrp) break;
            if (g + 1 < ngrp) LOADG(0, g + 1);
            CONSUME(1, g);
            g++;
            if (g >= ngrp) break;
        }
    }
    #undef LOADG
    #undef CONSUME

    *reinterpret_cast<float4*>(out + (size_t)row * D_CONST + lane * 4) =
        make_float4(facc[0], facc[1], facc[2], facc[3]);
    if (lane == 0) g_cursor[row] = 0;       // reset for next graph replay
}

// ---------------------------------------------------------------------------
// Inputs (metadata order):
//   0: subnode_ids [B*S] i32, 1: mask_batch [NNZ] i32, 2: mask_node [NNZ] i32,
//   3: mask_subnode [NNZ] i32, 4: mask_values [NNZ] f32, 5: emb_table [VOCAB*D] f32
// Output: [B*N*D] f32
// ---------------------------------------------------------------------------
extern "C" void kernel_launch(void* const* d_in, const int* in_sizes, int n_in,
                              void* d_out, int out_size) {
    const int*   subnode_ids  = (const int*)  d_in[0];
    const int*   mask_batch   = (const int*)  d_in[1];
    const int*   mask_node    = (const int*)  d_in[2];
    const int*   mask_subnode = (const int*)  d_in[3];
    const float* mask_values  = (const float*)d_in[4];
    const float* emb_table    = (const float*)d_in[5];
    float*       out          = (float*)d_out;

    prep_kernel<<<FILL_BLOCKS + CONV_BLOCKS, 256>>>(
        subnode_ids, mask_batch, mask_node, mask_subnode, mask_values, emb_table);

    // Accumulate with Programmatic Dependent Launch (overlaps prep's tail).
    cudaLaunchConfig_t cfg = {};
    cfg.gridDim  = dim3(ROWS / 4);
    cfg.blockDim = dim3(128);
    cfg.dynamicSmemBytes = 0;
    cfg.stream = 0;
    cudaLaunchAttribute attrs[1];
    attrs[0].id = cudaLaunchAttributeProgrammaticStreamSerialization;
    attrs[0].val.programmaticStreamSerializationAllowed = 1;
    cfg.attrs = attrs;
    cfg.numAttrs = 1;
    cudaLaunchKernelEx(&cfg, accumulate_kernel, out);
}